// round 1
// baseline (speedup 1.0000x reference)
#include <cuda_runtime.h>
#include <math.h>

// ---------------- problem constants ----------------
#define B_    4
#define NQ_   1024
#define NKV_  2048
#define H_    8
#define D_    288     // per-head feature dim: 16 mv-ch * 16 blades + 32 scalars
#define DP_   292     // padded smem stride (float4-aligned)
#define TQ_   32
#define TK_   32

__device__ constexpr int   GRADEA[16] = {0,1,1,1,1,2,2,2,2,2,2,3,3,3,3,4};
__device__ constexpr float METRICA[16] = {1.f,1.f,-1.f,-1.f,-1.f,-1.f,-1.f,-1.f,
                                          1.f,1.f, 1.f, 1.f, 1.f, 1.f,-1.f,-1.f};
__constant__ int GRADE_RT[16] = {0,1,1,1,1,2,2,2,2,2,2,3,3,3,3,4};

// ---------------- scratch (device globals; no cudaMalloc allowed) ----------------
// Q: [B][H][NQ][288], K/V: [B][H][NKV][288], O: [B][NQ][H][288]
__device__ float QB[(size_t)B_*H_*NQ_*D_];
__device__ float KB[(size_t)B_*H_*NKV_*D_];
__device__ float VB[(size_t)B_*H_*NKV_*D_];
__device__ float OB[(size_t)B_*NQ_*H_*D_];

// ============================================================================
// QKV projection: equi_linear for one token per block (128 threads).
// x_mv: [tok][16][16], x_s: [tok][32]
// w_mv: [128][16][5], w_s2mv: [128][32], w_mvs2s: [256][16], w_s2s: [256][32]
// Output written head-split: out[(b*8+head)*ntok + n][feat], feat = hid*16+x (mv), 256+hid (s)
// dst: 0=QB, 1=KB, 2=VB.  applyMetric multiplies mv features by METRIC[x] (K only).
// ============================================================================
__global__ void proj_kernel(const float* __restrict__ x_mv, const float* __restrict__ x_s,
                            const float* __restrict__ w_mv, const float* __restrict__ w_s2mv,
                            const float* __restrict__ w_mvs2s, const float* __restrict__ w_s2s,
                            const float* __restrict__ b_mv, const float* __restrict__ b_s,
                            int ntok, int dst, int applyMetric)
{
    __shared__ float xmv[256];
    __shared__ float xs[32];
    const int t   = blockIdx.x;
    const int b   = t / ntok;
    const int n   = t % ntok;
    const int tid = threadIdx.x;   // 128 threads

    const float* xp = x_mv + (size_t)t * 256;
    xmv[tid]       = xp[tid];
    xmv[tid + 128] = xp[tid + 128];
    if (tid < 32) xs[tid] = x_s[(size_t)t * 32 + tid];
    __syncthreads();

    float* out = (dst == 0) ? QB : (dst == 1) ? KB : VB;

    // ---- multivector output channel o = tid (0..127) ----
    {
        const int o = tid;
        const float* wr = w_mv + o * 80;   // [16][5]
        float y[16];
#pragma unroll
        for (int x = 0; x < 16; ++x) {
            float acc = 0.f;
#pragma unroll
            for (int i = 0; i < 16; ++i)
                acc += xmv[i * 16 + x] * wr[i * 5 + GRADEA[x]];
            y[x] = acc;
        }
        // scalar -> mv (blade 0) + bias
        float a0 = b_mv[o];
        const float* ws = w_s2mv + o * 32;
#pragma unroll
        for (int s = 0; s < 32; ++s) a0 += xs[s] * ws[s];
        y[0] += a0;

        const int head = o & 7, hid = o >> 3;
        float* op = out + ((size_t)(b * 8 + head) * ntok + n) * D_ + hid * 16;
        if (applyMetric) {
#pragma unroll
            for (int x = 0; x < 16; ++x) op[x] = y[x] * METRICA[x];
        } else {
#pragma unroll
            for (int x = 0; x < 16; ++x) op[x] = y[x];
        }
    }

    // ---- scalar outputs o = 2*tid, 2*tid+1 (0..255) ----
#pragma unroll
    for (int r = 0; r < 2; ++r) {
        const int o = tid * 2 + r;
        float y = b_s[o];
        const float* wm = w_mvs2s + o * 16;
#pragma unroll
        for (int i = 0; i < 16; ++i) y += xmv[i * 16] * wm[i];
        const float* ws = w_s2s + o * 32;
#pragma unroll
        for (int s = 0; s < 32; ++s) y += xs[s] * ws[s];
        const int head = o & 7, hid = o >> 3;
        out[((size_t)(b * 8 + head) * ntok + n) * D_ + 256 + hid] = y;
    }
}

// ============================================================================
// Flash attention (fp32, online softmax).
// grid = (NQ/TQ, B*H), block = 256.
// Thread (ty=tid/16, tx=tid%15) computes scores for queries {ty, ty+16} x keys
// {tx, tx+16}; AV phase: same 2 queries, dim slice {tx + 16*j, j<18}, acc in regs.
// ============================================================================
__global__ void attn_kernel()
{
    extern __shared__ float sm[];
    float* Qs  = sm;                    // TQ*DP
    float* Ks  = Qs + TQ_ * DP_;        // TK*DP
    float* Vs  = Ks + TK_ * DP_;        // TK*DP
    float* Ps  = Vs + TK_ * DP_;        // TQ*TK
    float* msm = Ps + TQ_ * TK_;        // TQ
    float* lsm = msm + TQ_;             // TQ

    const int qt  = blockIdx.x;
    const int bh  = blockIdx.y;
    const int tid = threadIdx.x;

    const float* Qp = QB + ((size_t)bh * NQ_ + qt * TQ_) * D_;
    const float* Kp = KB + (size_t)bh * NKV_ * D_;
    const float* Vp = VB + (size_t)bh * NKV_ * D_;

    for (int idx = tid; idx < TQ_ * D_; idx += 256) {
        int q = idx / D_, d = idx % D_;
        Qs[q * DP_ + d] = Qp[idx];
    }
    if (tid < TQ_) { msm[tid] = -1e30f; lsm[tid] = 0.f; }

    const int ty = tid >> 4, tx = tid & 15;
    const int q0 = ty, q1 = ty + 16;

    float acc0[18], acc1[18];
#pragma unroll
    for (int j = 0; j < 18; ++j) { acc0[j] = 0.f; acc1[j] = 0.f; }
    __syncthreads();

    const float SCALE = 0.0589255650988789f;  // 1/sqrt(288)

    for (int kt = 0; kt < NKV_ / TK_; ++kt) {
        const float* kp = Kp + (size_t)kt * TK_ * D_;
        const float* vp = Vp + (size_t)kt * TK_ * D_;
        for (int idx = tid; idx < TK_ * D_; idx += 256) {
            int r = idx / D_, d = idx % D_;
            Ks[r * DP_ + d] = kp[idx];
            Vs[r * DP_ + d] = vp[idx];
        }
        __syncthreads();

        // ---- scores: 2x2 micro-tile ----
        float s00 = 0.f, s01 = 0.f, s10 = 0.f, s11 = 0.f;
        const float4* qa = (const float4*)(Qs + q0 * DP_);
        const float4* qb = (const float4*)(Qs + q1 * DP_);
        const float4* ka = (const float4*)(Ks + tx * DP_);
        const float4* kb = (const float4*)(Ks + (tx + 16) * DP_);
#pragma unroll 8
        for (int d4 = 0; d4 < D_ / 4; ++d4) {
            float4 A = qa[d4], Bv = qb[d4], C = ka[d4], Dv = kb[d4];
            s00 += A.x*C.x + A.y*C.y + A.z*C.z + A.w*C.w;
            s01 += A.x*Dv.x + A.y*Dv.y + A.z*Dv.z + A.w*Dv.w;
            s10 += Bv.x*C.x + Bv.y*C.y + Bv.z*C.z + Bv.w*C.w;
            s11 += Bv.x*Dv.x + Bv.y*Dv.y + Bv.z*Dv.z + Bv.w*Dv.w;
        }
        s00 *= SCALE; s01 *= SCALE; s10 *= SCALE; s11 *= SCALE;

        // ---- online softmax ----
        float t0 = fmaxf(s00, s01), t1 = fmaxf(s10, s11);
#pragma unroll
        for (int off = 8; off; off >>= 1) {
            t0 = fmaxf(t0, __shfl_xor_sync(0xffffffffu, t0, off, 16));
            t1 = fmaxf(t1, __shfl_xor_sync(0xffffffffu, t1, off, 16));
        }
        const float mo0 = msm[q0], mo1 = msm[q1];
        const float mn0 = fmaxf(mo0, t0), mn1 = fmaxf(mo1, t1);
        const float al0 = __expf(mo0 - mn0), al1 = __expf(mo1 - mn1);
        const float p00 = __expf(s00 - mn0), p01 = __expf(s01 - mn0);
        const float p10 = __expf(s10 - mn1), p11 = __expf(s11 - mn1);
        Ps[q0 * TK_ + tx]      = p00;
        Ps[q0 * TK_ + tx + 16] = p01;
        Ps[q1 * TK_ + tx]      = p10;
        Ps[q1 * TK_ + tx + 16] = p11;
        float r0 = p00 + p01, r1 = p10 + p11;
#pragma unroll
        for (int off = 8; off; off >>= 1) {
            r0 += __shfl_xor_sync(0xffffffffu, r0, off, 16);
            r1 += __shfl_xor_sync(0xffffffffu, r1, off, 16);
        }
        __syncwarp();
        if (tx == 0) {
            lsm[q0] = lsm[q0] * al0 + r0; msm[q0] = mn0;
            lsm[q1] = lsm[q1] * al1 + r1; msm[q1] = mn1;
        }
        __syncthreads();

        // ---- AV accumulation (acc in registers) ----
#pragma unroll
        for (int j = 0; j < 18; ++j) { acc0[j] *= al0; acc1[j] *= al1; }
        for (int ki = 0; ki < TK_; ++ki) {
            const float pv0 = Ps[q0 * TK_ + ki];
            const float pv1 = Ps[q1 * TK_ + ki];
            const float* vr = Vs + ki * DP_ + tx;
#pragma unroll
            for (int j = 0; j < 18; ++j) {
                float v = vr[16 * j];
                acc0[j] += pv0 * v;
                acc1[j] += pv1 * v;
            }
        }
        __syncthreads();
    }

    const float inv0 = 1.0f / lsm[q0];
    const float inv1 = 1.0f / lsm[q1];
    const int b = bh >> 3, h = bh & 7;
    const size_t base0 = (((size_t)(b * NQ_ + qt * TQ_ + q0)) * 8 + h) * D_;
    const size_t base1 = (((size_t)(b * NQ_ + qt * TQ_ + q1)) * 8 + h) * D_;
#pragma unroll
    for (int j = 0; j < 18; ++j) {
        OB[base0 + tx + 16 * j] = acc0[j] * inv0;
        OB[base1 + tx + 16 * j] = acc1[j] * inv1;
    }
}

// ============================================================================
// Output projection. One token per block (256 threads). Reads OB, writes d_out:
// [out_mv (4,1024,16,16)] then [out_s (4,1024,32)], concatenated.
// Recombine mapping: mv channel c = head*16 + hid, scalar c = head*32 + hid.
// ============================================================================
__global__ void outproj_kernel(const float* __restrict__ wo_mv, const float* __restrict__ wo_s2mv,
                               const float* __restrict__ wo_mvs2s, const float* __restrict__ wo_s2s,
                               const float* __restrict__ bo_mv, const float* __restrict__ bo_s,
                               float* __restrict__ d_out)
{
    __shared__ float xm[2048];   // [c=128][x=16]
    __shared__ float xsc[256];
    const int t   = blockIdx.x;
    const int tid = threadIdx.x;  // 256
    const float* ob = OB + (size_t)t * 8 * D_;

    for (int idx = tid; idx < 2048; idx += 256) {
        const int c = idx >> 4, x = idx & 15;
        const int head = c >> 4, hid = c & 15;
        xm[idx] = ob[head * D_ + hid * 16 + x];
    }
    {
        const int head = tid >> 5, hid = tid & 31;
        xsc[tid] = ob[head * D_ + 256 + hid];
    }
    __syncthreads();

    // out_mv: o = tid/16, x = tid%16
    {
        const int o = tid >> 4, x = tid & 15;
        const int g = GRADE_RT[x];
        const float* w = wo_mv + (size_t)o * 128 * 5 + g;
        float y = 0.f;
#pragma unroll 8
        for (int i = 0; i < 128; ++i) y += xm[i * 16 + x] * w[i * 5];
        if (x == 0) {
            float a = bo_mv[o];
            const float* ws = wo_s2mv + o * 256;
#pragma unroll 8
            for (int s = 0; s < 256; ++s) a += xsc[s] * ws[s];
            y += a;
        }
        d_out[(size_t)t * 256 + o * 16 + x] = y;
    }
    // out_s: threads 0..31
    if (tid < 32) {
        const int o = tid;
        float y = bo_s[o];
        const float* wm = wo_mvs2s + o * 128;
#pragma unroll 8
        for (int i = 0; i < 128; ++i) y += xm[i * 16] * wm[i];
        const float* ws = wo_s2s + o * 256;
#pragma unroll 8
        for (int s = 0; s < 256; ++s) y += xsc[s] * ws[s];
        d_out[(size_t)B_ * NQ_ * 256 + (size_t)t * 32 + o] = y;
    }
}

// ============================================================================
// Host entry
// ============================================================================
extern "C" void kernel_launch(void* const* d_in, const int* in_sizes, int n_in,
                              void* d_out, int out_size)
{
    (void)in_sizes; (void)n_in; (void)out_size;

    const float* mv_kv = (const float*)d_in[0];
    const float* mv_q  = (const float*)d_in[1];
    const float* s_kv  = (const float*)d_in[2];
    const float* s_q   = (const float*)d_in[3];

    const float** W = (const float**)(d_in + 4);  // 6 per group: q, k, v, o
    const float* wq_mv = (const float*)d_in[4],  *wq_s2mv = (const float*)d_in[5];
    const float* wq_m2s = (const float*)d_in[6], *wq_s2s = (const float*)d_in[7];
    const float* bq_mv = (const float*)d_in[8],  *bq_s = (const float*)d_in[9];
    const float* wk_mv = (const float*)d_in[10], *wk_s2mv = (const float*)d_in[11];
    const float* wk_m2s = (const float*)d_in[12],*wk_s2s = (const float*)d_in[13];
    const float* bk_mv = (const float*)d_in[14], *bk_s = (const float*)d_in[15];
    const float* wv_mv = (const float*)d_in[16], *wv_s2mv = (const float*)d_in[17];
    const float* wv_m2s = (const float*)d_in[18],*wv_s2s = (const float*)d_in[19];
    const float* bv_mv = (const float*)d_in[20], *bv_s = (const float*)d_in[21];
    const float* wo_mv = (const float*)d_in[22], *wo_s2mv = (const float*)d_in[23];
    const float* wo_m2s = (const float*)d_in[24],*wo_s2s = (const float*)d_in[25];
    const float* bo_mv = (const float*)d_in[26], *bo_s = (const float*)d_in[27];
    (void)W;

    const size_t attn_smem = (size_t)(TQ_ * DP_ + 2 * TK_ * DP_ + TQ_ * TK_ + 2 * TQ_) * sizeof(float);
    cudaFuncSetAttribute(attn_kernel, cudaFuncAttributeMaxDynamicSharedMemorySize, (int)attn_smem);

    proj_kernel<<<B_ * NQ_, 128>>>(mv_q, s_q, wq_mv, wq_s2mv, wq_m2s, wq_s2s, bq_mv, bq_s,
                                   NQ_, 0, 0);
    proj_kernel<<<B_ * NKV_, 128>>>(mv_kv, s_kv, wk_mv, wk_s2mv, wk_m2s, wk_s2s, bk_mv, bk_s,
                                    NKV_, 1, 1);
    proj_kernel<<<B_ * NKV_, 128>>>(mv_kv, s_kv, wv_mv, wv_s2mv, wv_m2s, wv_s2s, bv_mv, bv_s,
                                    NKV_, 2, 0);

    attn_kernel<<<dim3(NQ_ / TQ_, B_ * H_), 256, attn_smem>>>();

    outproj_kernel<<<B_ * NQ_, 256>>>(wo_mv, wo_s2mv, wo_m2s, wo_s2s, bo_mv, bo_s,
                                      (float*)d_out);
}